// round 13
// baseline (speedup 1.0000x reference)
#include <cuda_runtime.h>
#include <cuda_fp16.h>
#include <cstdint>

// ============================================================================
// Problem constants: l=4, B=64, K=32, D=128 -> N=2048 rows per side, 2N=4096
// ============================================================================
#define L_LAYERS 4
#define N_HALF   2048
#define N_FULL   4096
#define DIM      128
#define TEMP_INV 5.0f
#define EXP_SCALE 7.2134752044448169f   // (1/T)*log2(e)

// Tile config: 128x128 sim tile per CTA, 8 warps in 2(m) x 4(n), 64x32 each
#define TM 128
#define TN 128
#define TDIM 32                                 // tiles per side
#define TRI_TILES (TDIM * (TDIM + 1) / 2)       // 528 upper-tri tiles per layer

#define REDUCE_BLOCKS 64

// ============================================================================
// Device scratch (allocation-free rule: __device__ globals)
// ============================================================================
__device__ __half g_z[(size_t)L_LAYERS * N_FULL * DIM];         // normalized reps (fp16)
__device__ float g_pos[L_LAYERS * N_HALF];                      // fp32 positives (exact)
__device__ float g_S[L_LAYERS * N_FULL];                        // per-row exp sums
__device__ double g_tot;                                        // loss accumulator
__device__ unsigned int g_ticket;                               // last-block-done counter

// ============================================================================
// Helpers
// ============================================================================
__device__ __forceinline__ uint32_t smem_to_u32(const void* smem_ptr) {
    uint32_t addr;
    asm("{ .reg .u64 tmp; cvta.to.shared.u64 tmp, %1; cvt.u32.u64 %0, tmp; }"
        : "=r"(addr) : "l"(smem_ptr));
    return addr;
}

__device__ __forceinline__ void cp_async16(uint32_t dst, const void* src) {
    asm volatile("cp.async.cg.shared.global [%0], [%1], 16;"
                 :: "r"(dst), "l"(src) : "memory");
}
__device__ __forceinline__ void cp_async_commit() {
    asm volatile("cp.async.commit_group;" ::: "memory");
}
template <int N>
__device__ __forceinline__ void cp_async_wait() {
    asm volatile("cp.async.wait_group %0;" :: "n"(N) : "memory");
}

__device__ __forceinline__ void ldmatrix_x4(uint32_t& r0, uint32_t& r1,
                                            uint32_t& r2, uint32_t& r3, uint32_t addr) {
    asm volatile("ldmatrix.sync.aligned.m8n8.x4.shared.b16 {%0,%1,%2,%3}, [%4];"
                 : "=r"(r0), "=r"(r1), "=r"(r2), "=r"(r3) : "r"(addr));
}

// fp16 MMA with fp16 accumulate: m16n8k16, D/C are 2 regs (4 halves).
// reg0 = {c0, c1} @ row q; reg1 = {c2, c3} @ row q+8 (cols 2qq, 2qq+1).
__device__ __forceinline__ void mma_f16acc(uint32_t* d, const uint32_t* a, const uint32_t* b) {
    asm volatile(
        "mma.sync.aligned.m16n8k16.row.col.f16.f16.f16.f16 "
        "{%0,%1}, {%2,%3,%4,%5}, {%6,%7}, {%0,%1};"
        : "+r"(d[0]), "+r"(d[1])
        : "r"(a[0]), "r"(a[1]), "r"(a[2]), "r"(a[3]), "r"(b[0]), "r"(b[1]));
}

// two exponentials per MUFU op: ex2.approx.f16x2
__device__ __forceinline__ __half2 h2_exp2(__half2 x) {
    __half2 y;
    asm("ex2.approx.f16x2 %0, %1;" : "=r"(*(uint32_t*)&y) : "r"(*(uint32_t*)&x));
    return y;
}

// shuffle a __half2 (as uint32) and hadd2-combine
__device__ __forceinline__ __half2 h2_shfl_add(__half2 v, int mask) {
    uint32_t u = *(uint32_t*)&v;
    uint32_t o = __shfl_xor_sync(0xFFFFFFFFu, u, mask);
    return __hadd2(v, *(__half2*)&o);
}

// ============================================================================
// Kernel 1: L2-normalize -> fp16 g_z, fp32 positives, zero g_S/g_tot/g_ticket
// one warp per (layer, n) pair; 2048 blocks x 128 threads (proven 27-reg form).
// ============================================================================
__global__ void norm_kernel(const float* __restrict__ ei, const float* __restrict__ ej) {
    int gt = blockIdx.x * 128 + threadIdx.x;
    if (gt < L_LAYERS * N_FULL) g_S[gt] = 0.0f;
    if (gt == 0) { g_tot = 0.0; g_ticket = 0u; }

    int gw = blockIdx.x * 4 + (threadIdx.x >> 5);
    int lane = threadIdx.x & 31;
    if (gw >= L_LAYERS * N_HALF) return;
    int layer = gw >> 11;
    int n = gw & (N_HALF - 1);

    const float4* ai = (const float4*)(ei + ((size_t)(layer * N_HALF + n)) * DIM);
    const float4* aj = (const float4*)(ej + ((size_t)(layer * N_HALF + n)) * DIM);
    float4 fi = ai[lane];
    float4 fj = aj[lane];
    float si = fi.x * fi.x + fi.y * fi.y + fi.z * fi.z + fi.w * fi.w;
    float sj = fj.x * fj.x + fj.y * fj.y + fj.z * fj.z + fj.w * fj.w;
    float dp = fi.x * fj.x + fi.y * fj.y + fi.z * fj.z + fi.w * fj.w;
#pragma unroll
    for (int o = 16; o; o >>= 1) {
        si += __shfl_xor_sync(0xFFFFFFFFu, si, o);
        sj += __shfl_xor_sync(0xFFFFFFFFu, sj, o);
        dp += __shfl_xor_sync(0xFFFFFFFFu, dp, o);
    }
    float inv_i = 1.0f / fmaxf(sqrtf(si), 1e-12f);
    float inv_j = 1.0f / fmaxf(sqrtf(sj), 1e-12f);

    __half* zi = g_z + ((size_t)layer * N_FULL + n) * DIM;
    __half* zj = g_z + ((size_t)layer * N_FULL + N_HALF + n) * DIM;
    ((__half2*)zi)[lane * 2]     = __floats2half2_rn(fi.x * inv_i, fi.y * inv_i);
    ((__half2*)zi)[lane * 2 + 1] = __floats2half2_rn(fi.z * inv_i, fi.w * inv_i);
    ((__half2*)zj)[lane * 2]     = __floats2half2_rn(fj.x * inv_j, fj.y * inv_j);
    ((__half2*)zj)[lane * 2 + 1] = __floats2half2_rn(fj.z * inv_j, fj.w * inv_j);
    if (lane == 0) g_pos[layer * N_HALF + n] = dp * inv_i * inv_j;
}

// ============================================================================
// Kernel 2: symmetric fused sim + exp + row/col sums (HMMA fp16, f16 accum).
// Upper-triangular tiles only. cp.async 2-stage K pipeline (64-col halves).
// 256 threads, 8 warps in 2x4, 64x32 per warp. 3 CTAs/SM (24 warps/SM).
// ============================================================================
static constexpr int SMEM_A = 0;
static constexpr int SMEM_B = 128 * 256;             // 32 KB
static constexpr int SMEM_TOTAL = 2 * 128 * 256;     // 64 KB

__global__ void __launch_bounds__(256, 3)
sim_kernel() {
    extern __shared__ char smem[];
    uint32_t sbase = smem_to_u32(smem);
    int tid = threadIdx.x;
    int wid = tid >> 5;
    int lane = tid & 31;

    int t = blockIdx.x;
    int layer = t / TRI_TILES;
    int u = t - layer * TRI_TILES;      // 0..527 upper-tri index
    int rowt = (int)((65.0f - sqrtf(65.0f * 65.0f - 8.0f * (float)u)) * 0.5f);
    while ((rowt + 1) * TDIM - ((rowt + 1) * rowt) / 2 <= u) rowt++;
    while (rowt * TDIM - (rowt * (rowt - 1)) / 2 > u) rowt--;
    int colt = rowt + (u - (rowt * TDIM - (rowt * (rowt - 1)) / 2));
    int r0 = rowt * TM;
    int c0 = colt * TN;
    bool diag_tile = (rowt == colt);

    const __half* zl = g_z + (size_t)layer * N_FULL * DIM;

    // ---- cp.async 2-stage pipeline: half h covers 16B-chunks h*8..h*8+7 ----
#pragma unroll
    for (int h = 0; h < 2; h++) {
#pragma unroll
        for (int it = 0; it < 4; it++) {
            int idx = tid + it * 256;        // 1024 chunks per tile-half
            int row = idx >> 3;
            int c = idx & 7;
            int ch = h * 8 + c;
            uint32_t dst_off = (uint32_t)row * 256 + (uint32_t)((ch ^ (row & 7)) * 16);
            cp_async16(sbase + SMEM_A + dst_off, zl + (size_t)(r0 + row) * DIM + ch * 8);
            cp_async16(sbase + SMEM_B + dst_off, zl + (size_t)(c0 + row) * DIM + ch * 8);
        }
        cp_async_commit();
    }

    // ---- Warp tiling: wm in {0,1}, wn in {0..3}; warp covers 64x32 ----
    int wm = wid >> 2;
    int wn = wid & 3;

    uint32_t acc[4][4][2];               // f16x2 accumulators
#pragma unroll
    for (int mt = 0; mt < 4; mt++)
#pragma unroll
        for (int nt = 0; nt < 4; nt++) { acc[mt][nt][0] = 0u; acc[mt][nt][1] = 0u; }

    int lr = lane & 7;
    int g = lane >> 3;
    int a_row_off = lr + ((g & 1) << 3);
    int a_chalf = g >> 1;
    int b_row_off = lr + ((lane >> 4) << 3);
    int b_chalf = (lane >> 3) & 1;

#pragma unroll
    for (int half = 0; half < 2; half++) {
        if (half == 0) cp_async_wait<1>(); else cp_async_wait<0>();
        __syncthreads();
#pragma unroll
        for (int kk = 0; kk < 4; kk++) {
            int ks = half * 4 + kk;
            uint32_t a[4][4];
#pragma unroll
            for (int mt = 0; mt < 4; mt++) {
                int r = wm * 64 + mt * 16 + a_row_off;
                int ch = 2 * ks + a_chalf;
                uint32_t addr = sbase + SMEM_A + (uint32_t)r * 256
                              + (uint32_t)((ch ^ (r & 7)) * 16);
                ldmatrix_x4(a[mt][0], a[mt][1], a[mt][2], a[mt][3], addr);
            }
            uint32_t b[4][2];
#pragma unroll
            for (int np = 0; np < 2; np++) {     // pairs of 8-col n-tiles
                int n = wn * 32 + np * 16 + b_row_off;
                int ch = 2 * ks + b_chalf;
                uint32_t addr = sbase + SMEM_B + (uint32_t)n * 256
                              + (uint32_t)((ch ^ (n & 7)) * 16);
                ldmatrix_x4(b[2 * np][0], b[2 * np][1], b[2 * np + 1][0], b[2 * np + 1][1], addr);
            }
#pragma unroll
            for (int mt = 0; mt < 4; mt++)
#pragma unroll
                for (int nt = 0; nt < 4; nt++)
                    mma_f16acc(acc[mt][nt], a[mt], b[nt]);
        }
    }

    // ---- Epilogue ----
    int q = lane >> 2;       // accum row within 8
    int qq = lane & 3;       // accum col quad
    float* S = g_S + layer * N_FULL;
    const __half2 scale_h2 = __float2half2_rn(EXP_SCALE);

    if (diag_tile) {
        // masked f32 path (identity diagonal lives here; only 32/528 tiles)
#pragma unroll
        for (int mt = 0; mt < 4; mt++) {
            int gr0 = r0 + wm * 64 + mt * 16 + q;
            int gr1 = gr0 + 8;
            float s0 = 0.0f, s1 = 0.0f;
#pragma unroll
            for (int nt = 0; nt < 4; nt++) {
                int gcb = c0 + wn * 32 + nt * 8 + qq * 2;
                float2 f01 = __half22float2(h2_exp2(__hmul2(*(__half2*)&acc[mt][nt][0], scale_h2)));
                float2 f23 = __half22float2(h2_exp2(__hmul2(*(__half2*)&acc[mt][nt][1], scale_h2)));
                if (gcb     != gr0) s0 += f01.x;
                if (gcb + 1 != gr0) s0 += f01.y;
                if (gcb     != gr1) s1 += f23.x;
                if (gcb + 1 != gr1) s1 += f23.y;
            }
            s0 += __shfl_xor_sync(0xFFFFFFFFu, s0, 1);
            s0 += __shfl_xor_sync(0xFFFFFFFFu, s0, 2);
            s1 += __shfl_xor_sync(0xFFFFFFFFu, s1, 1);
            s1 += __shfl_xor_sync(0xFFFFFFFFu, s1, 2);
            if (qq == 0) {
                atomicAdd(&S[gr0], s0);
                atomicAdd(&S[gr1], s1);
            }
        }
    } else {
        // packed path: e01 lanes share row gr0; e23 lanes share row gr1;
        // (e01 + e23) lanes are the two column partials.
        __half2 cs_h2[4];
#pragma unroll
        for (int nt = 0; nt < 4; nt++) cs_h2[nt] = __float2half2_rn(0.0f);
#pragma unroll
        for (int mt = 0; mt < 4; mt++) {
            int gr0 = r0 + wm * 64 + mt * 16 + q;
            int gr1 = gr0 + 8;
            __half2 r0h = __float2half2_rn(0.0f);
            __half2 r1h = __float2half2_rn(0.0f);
#pragma unroll
            for (int nt = 0; nt < 4; nt++) {
                __half2 e01 = h2_exp2(__hmul2(*(__half2*)&acc[mt][nt][0], scale_h2));
                __half2 e23 = h2_exp2(__hmul2(*(__half2*)&acc[mt][nt][1], scale_h2));
                r0h = __hadd2(r0h, e01);
                r1h = __hadd2(r1h, e23);
                cs_h2[nt] = __hadd2(cs_h2[nt], __hadd2(e01, e23));
            }
            float s0 = __low2float(r0h) + __high2float(r0h);
            float s1 = __low2float(r1h) + __high2float(r1h);
            s0 += __shfl_xor_sync(0xFFFFFFFFu, s0, 1);
            s0 += __shfl_xor_sync(0xFFFFFFFFu, s0, 2);
            s1 += __shfl_xor_sync(0xFFFFFFFFu, s1, 1);
            s1 += __shfl_xor_sync(0xFFFFFFFFu, s1, 2);
            if (qq == 0) {
                atomicAdd(&S[gr0], s0);
                atomicAdd(&S[gr1], s1);
            }
        }
        // column sums: packed half2 shuffles over q (xor 4,8,16)
#pragma unroll
        for (int nt = 0; nt < 4; nt++) {
            __half2 c = cs_h2[nt];
            c = h2_shfl_add(c, 4);
            c = h2_shfl_add(c, 8);
            c = h2_shfl_add(c, 16);
            if (q == 0) {
                atomicAdd(&S[c0 + wn * 32 + nt * 8 + qq * 2],     __low2float(c));
                atomicAdd(&S[c0 + wn * 32 + nt * 8 + qq * 2 + 1], __high2float(c));
            }
        }
    }
}

// ============================================================================
// Kernel 3: loss reduction + last-block finalize
// ============================================================================
__global__ void reduce_kernel(const float* __restrict__ jv, float* __restrict__ out) {
    __shared__ float sh[256];
    __shared__ bool is_last;
    int tid = threadIdx.x;
    int i = blockIdx.x * 256 + tid;          // 0..16383
    int layer = i >> 12;
    int n = i & (N_FULL - 1);
    int m = n & (N_HALF - 1);
    float w = jv[m];
    float lp = logf(g_S[i]) - g_pos[layer * N_HALF + m] * TEMP_INV;
    sh[tid] = w * lp;
    __syncthreads();
    for (int o = 128; o; o >>= 1) {
        if (tid < o) sh[tid] += sh[tid + o];
        __syncthreads();
    }
    if (tid == 0) {
        atomicAdd(&g_tot, (double)sh[0]);
        __threadfence();
        unsigned int done = atomicAdd(&g_ticket, 1u);
        is_last = (done == REDUCE_BLOCKS - 1);
    }
    __syncthreads();

    if (is_last) {
        float num = 0.0f;
        for (int k = tid; k < N_HALF; k += 256) num += jv[k];
        sh[tid] = num;
        __syncthreads();
        for (int o = 128; o; o >>= 1) {
            if (tid < o) sh[tid] += sh[tid + o];
            __syncthreads();
        }
        if (tid == 0) {
            double tot = *((volatile double*)&g_tot);
            out[0] = (float)(tot / (2.0 * (double)sh[0]));
        }
    }
}

// ============================================================================
// Launch
// ============================================================================
extern "C" void kernel_launch(void* const* d_in, const int* in_sizes, int n_in,
                              void* d_out, int out_size) {
    const float* ei = (const float*)d_in[0];
    const float* ej = (const float*)d_in[1];
    const float* jv = (const float*)d_in[2];
    float* out = (float*)d_out;

    cudaFuncSetAttribute(sim_kernel, cudaFuncAttributeMaxDynamicSharedMemorySize, SMEM_TOTAL);

    norm_kernel<<<(L_LAYERS * N_HALF) / 4, 128>>>(ei, ej);
    sim_kernel<<<L_LAYERS * TRI_TILES, 256, SMEM_TOTAL>>>();
    reduce_kernel<<<REDUCE_BLOCKS, 256>>>(jv, out);
}

// round 14
// speedup vs baseline: 1.0128x; 1.0128x over previous
#include <cuda_runtime.h>
#include <cuda_fp16.h>
#include <cstdint>

// ============================================================================
// Problem constants: l=4, B=64, K=32, D=128 -> N=2048 rows per side, 2N=4096
// ============================================================================
#define L_LAYERS 4
#define N_HALF   2048
#define N_FULL   4096
#define DIM      128
#define TEMP_INV 5.0f
#define EXP_SCALE 7.2134752044448169f   // (1/T)*log2(e)

// Tile config: 128x128 sim tile per CTA, 4 warps in 2(m) x 2(n), 64x64 each
#define TM 128
#define TN 128
#define TDIM 32                                 // tiles per side
#define TRI_TILES (TDIM * (TDIM + 1) / 2)       // 528 upper-tri tiles per layer

#define REDUCE_BLOCKS 64

// ============================================================================
// Device scratch (allocation-free rule: __device__ globals)
// ============================================================================
__device__ __half g_z[(size_t)L_LAYERS * N_FULL * DIM];         // normalized reps (fp16)
__device__ float g_pos[L_LAYERS * N_HALF];                      // fp32 positives (exact)
__device__ float g_S[L_LAYERS * N_FULL];                        // per-row exp sums
__device__ double g_tot;                                        // loss accumulator
__device__ unsigned int g_ticket;                               // last-block-done counter

// ============================================================================
// Helpers
// ============================================================================
__device__ __forceinline__ uint32_t smem_to_u32(const void* smem_ptr) {
    uint32_t addr;
    asm("{ .reg .u64 tmp; cvta.to.shared.u64 tmp, %1; cvt.u32.u64 %0, tmp; }"
        : "=r"(addr) : "l"(smem_ptr));
    return addr;
}

__device__ __forceinline__ void cp_async16(uint32_t dst, const void* src) {
    asm volatile("cp.async.cg.shared.global [%0], [%1], 16;"
                 :: "r"(dst), "l"(src) : "memory");
}
__device__ __forceinline__ void cp_async_commit() {
    asm volatile("cp.async.commit_group;" ::: "memory");
}
template <int N>
__device__ __forceinline__ void cp_async_wait() {
    asm volatile("cp.async.wait_group %0;" :: "n"(N) : "memory");
}

__device__ __forceinline__ void ldmatrix_x4(uint32_t& r0, uint32_t& r1,
                                            uint32_t& r2, uint32_t& r3, uint32_t addr) {
    asm volatile("ldmatrix.sync.aligned.m8n8.x4.shared.b16 {%0,%1,%2,%3}, [%4];"
                 : "=r"(r0), "=r"(r1), "=r"(r2), "=r"(r3) : "r"(addr));
}

// fp16 MMA with fp16 accumulate: m16n8k16, D/C are 2 regs (4 halves).
// reg0 = {c0, c1} @ row q; reg1 = {c2, c3} @ row q+8 (cols 2qq, 2qq+1).
__device__ __forceinline__ void mma_f16acc(uint32_t* d, const uint32_t* a, const uint32_t* b) {
    asm volatile(
        "mma.sync.aligned.m16n8k16.row.col.f16.f16.f16.f16 "
        "{%0,%1}, {%2,%3,%4,%5}, {%6,%7}, {%0,%1};"
        : "+r"(d[0]), "+r"(d[1])
        : "r"(a[0]), "r"(a[1]), "r"(a[2]), "r"(a[3]), "r"(b[0]), "r"(b[1]));
}

// two exponentials per MUFU op: ex2.approx.f16x2
__device__ __forceinline__ __half2 h2_exp2(__half2 x) {
    __half2 y;
    asm("ex2.approx.f16x2 %0, %1;" : "=r"(*(uint32_t*)&y) : "r"(*(uint32_t*)&x));
    return y;
}

// shuffle a __half2 (as uint32) and hadd2-combine
__device__ __forceinline__ __half2 h2_shfl_add(__half2 v, int mask) {
    uint32_t u = *(uint32_t*)&v;
    uint32_t o = __shfl_xor_sync(0xFFFFFFFFu, u, mask);
    return __hadd2(v, *(__half2*)&o);
}

// ============================================================================
// Kernel 1: L2-normalize -> fp16 g_z, fp32 positives, zero g_S/g_tot/g_ticket
// one warp per (layer, n) pair; 2048 blocks x 128 threads (proven 27-reg form).
// ============================================================================
__global__ void norm_kernel(const float* __restrict__ ei, const float* __restrict__ ej) {
    int gt = blockIdx.x * 128 + threadIdx.x;
    if (gt < L_LAYERS * N_FULL) g_S[gt] = 0.0f;
    if (gt == 0) { g_tot = 0.0; g_ticket = 0u; }

    int gw = blockIdx.x * 4 + (threadIdx.x >> 5);
    int lane = threadIdx.x & 31;
    if (gw >= L_LAYERS * N_HALF) return;
    int layer = gw >> 11;
    int n = gw & (N_HALF - 1);

    const float4* ai = (const float4*)(ei + ((size_t)(layer * N_HALF + n)) * DIM);
    const float4* aj = (const float4*)(ej + ((size_t)(layer * N_HALF + n)) * DIM);
    float4 fi = ai[lane];
    float4 fj = aj[lane];
    float si = fi.x * fi.x + fi.y * fi.y + fi.z * fi.z + fi.w * fi.w;
    float sj = fj.x * fj.x + fj.y * fj.y + fj.z * fj.z + fj.w * fj.w;
    float dp = fi.x * fj.x + fi.y * fj.y + fi.z * fj.z + fi.w * fj.w;
#pragma unroll
    for (int o = 16; o; o >>= 1) {
        si += __shfl_xor_sync(0xFFFFFFFFu, si, o);
        sj += __shfl_xor_sync(0xFFFFFFFFu, sj, o);
        dp += __shfl_xor_sync(0xFFFFFFFFu, dp, o);
    }
    float inv_i = 1.0f / fmaxf(sqrtf(si), 1e-12f);
    float inv_j = 1.0f / fmaxf(sqrtf(sj), 1e-12f);

    __half* zi = g_z + ((size_t)layer * N_FULL + n) * DIM;
    __half* zj = g_z + ((size_t)layer * N_FULL + N_HALF + n) * DIM;
    ((__half2*)zi)[lane * 2]     = __floats2half2_rn(fi.x * inv_i, fi.y * inv_i);
    ((__half2*)zi)[lane * 2 + 1] = __floats2half2_rn(fi.z * inv_i, fi.w * inv_i);
    ((__half2*)zj)[lane * 2]     = __floats2half2_rn(fj.x * inv_j, fj.y * inv_j);
    ((__half2*)zj)[lane * 2 + 1] = __floats2half2_rn(fj.z * inv_j, fj.w * inv_j);
    if (lane == 0) g_pos[layer * N_HALF + n] = dp * inv_i * inv_j;
}

// ============================================================================
// Kernel 2: symmetric fused sim + exp + row/col sums (HMMA fp16, f16 accum).
// Upper-triangular tiles only. cp.async 2-stage K pipeline (64-col halves).
// 128 threads, 4 warps in 2x2, 64x64 per warp. 3 CTAs/SM.
// Epilogue fully packed: f16x2 exp + HADD2 partials + packed half2 shuffles.
// ============================================================================
static constexpr int SMEM_A = 0;
static constexpr int SMEM_B = 128 * 256;             // 32 KB
static constexpr int SMEM_TOTAL = 2 * 128 * 256;     // 64 KB

__global__ void __launch_bounds__(128, 3)
sim_kernel() {
    extern __shared__ char smem[];
    uint32_t sbase = smem_to_u32(smem);
    int tid = threadIdx.x;
    int wid = tid >> 5;
    int lane = tid & 31;

    int t = blockIdx.x;
    int layer = t / TRI_TILES;
    int u = t - layer * TRI_TILES;      // 0..527 upper-tri index
    int rowt = (int)((65.0f - sqrtf(65.0f * 65.0f - 8.0f * (float)u)) * 0.5f);
    while ((rowt + 1) * TDIM - ((rowt + 1) * rowt) / 2 <= u) rowt++;
    while (rowt * TDIM - (rowt * (rowt - 1)) / 2 > u) rowt--;
    int colt = rowt + (u - (rowt * TDIM - (rowt * (rowt - 1)) / 2));
    int r0 = rowt * TM;
    int c0 = colt * TN;
    bool diag_tile = (rowt == colt);

    const __half* zl = g_z + (size_t)layer * N_FULL * DIM;

    // ---- cp.async 2-stage pipeline: half h covers 16B-chunks h*8..h*8+7 ----
#pragma unroll
    for (int h = 0; h < 2; h++) {
#pragma unroll
        for (int it = 0; it < 8; it++) {
            int idx = tid + it * 128;        // 1024 chunks per tile-half
            int row = idx >> 3;
            int c = idx & 7;
            int ch = h * 8 + c;
            uint32_t dst_off = (uint32_t)row * 256 + (uint32_t)((ch ^ (row & 7)) * 16);
            cp_async16(sbase + SMEM_A + dst_off, zl + (size_t)(r0 + row) * DIM + ch * 8);
            cp_async16(sbase + SMEM_B + dst_off, zl + (size_t)(c0 + row) * DIM + ch * 8);
        }
        cp_async_commit();
    }

    // ---- Warp tiling: wm,wn in {0,1}; warp covers 64x64 ----
    int wm = wid >> 1;
    int wn = wid & 1;

    uint32_t acc[4][8][2];               // f16x2 accumulators
#pragma unroll
    for (int mt = 0; mt < 4; mt++)
#pragma unroll
        for (int nt = 0; nt < 8; nt++) { acc[mt][nt][0] = 0u; acc[mt][nt][1] = 0u; }

    int lr = lane & 7;
    int g = lane >> 3;
    int a_row_off = lr + ((g & 1) << 3);
    int a_chalf = g >> 1;
    int b_row_off = lr + ((lane >> 4) << 3);
    int b_chalf = (lane >> 3) & 1;

#pragma unroll
    for (int half = 0; half < 2; half++) {
        if (half == 0) cp_async_wait<1>(); else cp_async_wait<0>();
        __syncthreads();
#pragma unroll
        for (int kk = 0; kk < 4; kk++) {
            int ks = half * 4 + kk;
            uint32_t a[4][4];
#pragma unroll
            for (int mt = 0; mt < 4; mt++) {
                int r = wm * 64 + mt * 16 + a_row_off;
                int ch = 2 * ks + a_chalf;
                uint32_t addr = sbase + SMEM_A + (uint32_t)r * 256
                              + (uint32_t)((ch ^ (r & 7)) * 16);
                ldmatrix_x4(a[mt][0], a[mt][1], a[mt][2], a[mt][3], addr);
            }
            uint32_t b[8][2];
#pragma unroll
            for (int np = 0; np < 4; np++) {     // pairs of 8-col n-tiles
                int n = wn * 64 + np * 16 + b_row_off;
                int ch = 2 * ks + b_chalf;
                uint32_t addr = sbase + SMEM_B + (uint32_t)n * 256
                              + (uint32_t)((ch ^ (n & 7)) * 16);
                ldmatrix_x4(b[2 * np][0], b[2 * np][1], b[2 * np + 1][0], b[2 * np + 1][1], addr);
            }
#pragma unroll
            for (int mt = 0; mt < 4; mt++)
#pragma unroll
                for (int nt = 0; nt < 8; nt++)
                    mma_f16acc(acc[mt][nt], a[mt], b[nt]);
        }
    }

    // ---- Epilogue ----
    int q = lane >> 2;       // accum row within 8
    int qq = lane & 3;       // accum col quad
    float* S = g_S + layer * N_FULL;
    const __half2 scale_h2 = __float2half2_rn(EXP_SCALE);

    if (diag_tile) {
        // masked f32 path (identity diagonal lives here; only 32/528 tiles)
#pragma unroll
        for (int mt = 0; mt < 4; mt++) {
            int gr0 = r0 + wm * 64 + mt * 16 + q;
            int gr1 = gr0 + 8;
            float s0 = 0.0f, s1 = 0.0f;
#pragma unroll
            for (int nt = 0; nt < 8; nt++) {
                int gcb = c0 + wn * 64 + nt * 8 + qq * 2;
                float2 f01 = __half22float2(h2_exp2(__hmul2(*(__half2*)&acc[mt][nt][0], scale_h2)));
                float2 f23 = __half22float2(h2_exp2(__hmul2(*(__half2*)&acc[mt][nt][1], scale_h2)));
                if (gcb     != gr0) s0 += f01.x;
                if (gcb + 1 != gr0) s0 += f01.y;
                if (gcb     != gr1) s1 += f23.x;
                if (gcb + 1 != gr1) s1 += f23.y;
            }
            s0 += __shfl_xor_sync(0xFFFFFFFFu, s0, 1);
            s0 += __shfl_xor_sync(0xFFFFFFFFu, s0, 2);
            s1 += __shfl_xor_sync(0xFFFFFFFFu, s1, 1);
            s1 += __shfl_xor_sync(0xFFFFFFFFu, s1, 2);
            if (qq == 0) {
                atomicAdd(&S[gr0], s0);
                atomicAdd(&S[gr1], s1);
            }
        }
    } else {
        // fully packed path: e01 lanes share row gr0; e23 lanes share row gr1;
        // (e01 + e23) lanes are the two column partials.
        __half2 cs_h2[8];
#pragma unroll
        for (int nt = 0; nt < 8; nt++) cs_h2[nt] = __float2half2_rn(0.0f);
#pragma unroll
        for (int mt = 0; mt < 4; mt++) {
            int gr0 = r0 + wm * 64 + mt * 16 + q;
            __half2 r0h = __float2half2_rn(0.0f);
            __half2 r1h = __float2half2_rn(0.0f);
#pragma unroll
            for (int nt = 0; nt < 8; nt++) {
                __half2 e01 = h2_exp2(__hmul2(*(__half2*)&acc[mt][nt][0], scale_h2));
                __half2 e23 = h2_exp2(__hmul2(*(__half2*)&acc[mt][nt][1], scale_h2));
                r0h = __hadd2(r0h, e01);
                r1h = __hadd2(r1h, e23);
                cs_h2[nt] = __hadd2(cs_h2[nt], __hadd2(e01, e23));
            }
            // pack {row gr0 partial, row gr0+8 partial} into one half2, 2 packed shuffles
            __half2 rp = __halves2half2(__hadd(__low2half(r0h), __high2half(r0h)),
                                        __hadd(__low2half(r1h), __high2half(r1h)));
            rp = h2_shfl_add(rp, 1);
            rp = h2_shfl_add(rp, 2);
            if (qq == 0) {
                atomicAdd(&S[gr0],     __low2float(rp));
                atomicAdd(&S[gr0 + 8], __high2float(rp));
            }
        }
        // column sums: packed half2 shuffles over q (xor 4,8,16)
#pragma unroll
        for (int nt = 0; nt < 8; nt++) {
            __half2 c = cs_h2[nt];
            c = h2_shfl_add(c, 4);
            c = h2_shfl_add(c, 8);
            c = h2_shfl_add(c, 16);
            if (q == 0) {
                atomicAdd(&S[c0 + wn * 64 + nt * 8 + qq * 2],     __low2float(c));
                atomicAdd(&S[c0 + wn * 64 + nt * 8 + qq * 2 + 1], __high2float(c));
            }
        }
    }
}

// ============================================================================
// Kernel 3: loss reduction + last-block finalize
// ============================================================================
__global__ void reduce_kernel(const float* __restrict__ jv, float* __restrict__ out) {
    __shared__ float sh[256];
    __shared__ bool is_last;
    int tid = threadIdx.x;
    int i = blockIdx.x * 256 + tid;          // 0..16383
    int layer = i >> 12;
    int n = i & (N_FULL - 1);
    int m = n & (N_HALF - 1);
    float w = jv[m];
    float lp = logf(g_S[i]) - g_pos[layer * N_HALF + m] * TEMP_INV;
    sh[tid] = w * lp;
    __syncthreads();
    for (int o = 128; o; o >>= 1) {
        if (tid < o) sh[tid] += sh[tid + o];
        __syncthreads();
    }
    if (tid == 0) {
        atomicAdd(&g_tot, (double)sh[0]);
        __threadfence();
        unsigned int done = atomicAdd(&g_ticket, 1u);
        is_last = (done == REDUCE_BLOCKS - 1);
    }
    __syncthreads();

    if (is_last) {
        float num = 0.0f;
        for (int k = tid; k < N_HALF; k += 256) num += jv[k];
        sh[tid] = num;
        __syncthreads();
        for (int o = 128; o; o >>= 1) {
            if (tid < o) sh[tid] += sh[tid + o];
            __syncthreads();
        }
        if (tid == 0) {
            double tot = *((volatile double*)&g_tot);
            out[0] = (float)(tot / (2.0 * (double)sh[0]));
        }
    }
}

// ============================================================================
// Launch
// ============================================================================
extern "C" void kernel_launch(void* const* d_in, const int* in_sizes, int n_in,
                              void* d_out, int out_size) {
    const float* ei = (const float*)d_in[0];
    const float* ej = (const float*)d_in[1];
    const float* jv = (const float*)d_in[2];
    float* out = (float*)d_out;

    cudaFuncSetAttribute(sim_kernel, cudaFuncAttributeMaxDynamicSharedMemorySize, SMEM_TOTAL);

    norm_kernel<<<(L_LAYERS * N_HALF) / 4, 128>>>(ei, ej);
    sim_kernel<<<L_LAYERS * TRI_TILES, 128, SMEM_TOTAL>>>();
    reduce_kernel<<<REDUCE_BLOCKS, 256>>>(jv, out);
}

// round 15
// speedup vs baseline: 1.0524x; 1.0391x over previous
#include <cuda_runtime.h>
#include <cuda_fp16.h>
#include <cstdint>

// ============================================================================
// Problem constants: l=4, B=64, K=32, D=128 -> N=2048 rows per side, 2N=4096
// ============================================================================
#define L_LAYERS 4
#define N_HALF   2048
#define N_FULL   4096
#define DIM      128
#define TEMP_INV 5.0f
#define EXP_SCALE 7.2134752044448169f   // (1/T)*log2(e)

// Tile config: 128x128 sim tile per CTA, 4 warps in 2(m) x 2(n), 64x64 each
#define TM 128
#define TN 128
#define TDIM 32                                 // tiles per side
#define TRI_TILES (TDIM * (TDIM + 1) / 2)       // 528 upper-tri tiles per layer

#define REDUCE_BLOCKS 64

// ============================================================================
// Device scratch (allocation-free rule: __device__ globals)
// ============================================================================
__device__ __half g_z[(size_t)L_LAYERS * N_FULL * DIM];         // normalized reps (fp16)
__device__ float g_pos[L_LAYERS * N_HALF];                      // fp32 positives (exact)
__device__ float g_S[L_LAYERS * N_FULL];                        // per-row exp sums
__device__ double g_tot;                                        // loss accumulator
__device__ unsigned int g_ticket;                               // last-block-done counter

// ============================================================================
// Helpers
// ============================================================================
__device__ __forceinline__ uint32_t smem_to_u32(const void* smem_ptr) {
    uint32_t addr;
    asm("{ .reg .u64 tmp; cvta.to.shared.u64 tmp, %1; cvt.u32.u64 %0, tmp; }"
        : "=r"(addr) : "l"(smem_ptr));
    return addr;
}

__device__ __forceinline__ void cp_async16(uint32_t dst, const void* src) {
    asm volatile("cp.async.cg.shared.global [%0], [%1], 16;"
                 :: "r"(dst), "l"(src) : "memory");
}
__device__ __forceinline__ void cp_async_commit() {
    asm volatile("cp.async.commit_group;" ::: "memory");
}
template <int N>
__device__ __forceinline__ void cp_async_wait() {
    asm volatile("cp.async.wait_group %0;" :: "n"(N) : "memory");
}

__device__ __forceinline__ void ldmatrix_x4(uint32_t& r0, uint32_t& r1,
                                            uint32_t& r2, uint32_t& r3, uint32_t addr) {
    asm volatile("ldmatrix.sync.aligned.m8n8.x4.shared.b16 {%0,%1,%2,%3}, [%4];"
                 : "=r"(r0), "=r"(r1), "=r"(r2), "=r"(r3) : "r"(addr));
}

// fp16 MMA with fp16 accumulate: m16n8k16, D/C are 2 regs (4 halves).
// reg0 = {c0, c1} @ row q; reg1 = {c2, c3} @ row q+8 (cols 2qq, 2qq+1).
__device__ __forceinline__ void mma_f16acc(uint32_t* d, const uint32_t* a, const uint32_t* b) {
    asm volatile(
        "mma.sync.aligned.m16n8k16.row.col.f16.f16.f16.f16 "
        "{%0,%1}, {%2,%3,%4,%5}, {%6,%7}, {%0,%1};"
        : "+r"(d[0]), "+r"(d[1])
        : "r"(a[0]), "r"(a[1]), "r"(a[2]), "r"(a[3]), "r"(b[0]), "r"(b[1]));
}

// two exponentials per MUFU op: ex2.approx.f16x2
__device__ __forceinline__ __half2 h2_exp2(__half2 x) {
    __half2 y;
    asm("ex2.approx.f16x2 %0, %1;" : "=r"(*(uint32_t*)&y) : "r"(*(uint32_t*)&x));
    return y;
}

// shuffle a __half2 (as uint32) and hadd2-combine
__device__ __forceinline__ __half2 h2_shfl_add(__half2 v, int mask) {
    uint32_t u = *(uint32_t*)&v;
    uint32_t o = __shfl_xor_sync(0xFFFFFFFFu, u, mask);
    return __hadd2(v, *(__half2*)&o);
}

// ============================================================================
// Kernel 1: L2-normalize -> fp16 g_z, fp32 positives, zero g_S/g_tot/g_ticket
// EIGHT lanes per (layer, n) pair: each lane loads 4+4 float4 (MLP=8),
// 3-level shuffle reduce (xor 1,2,4). 512 blocks x 128 threads (16 pairs/blk).
// ============================================================================
__global__ void norm_kernel(const float* __restrict__ ei, const float* __restrict__ ej) {
    int gt = blockIdx.x * 128 + threadIdx.x;      // 0..65535
    if (gt < L_LAYERS * N_FULL) g_S[gt] = 0.0f;
    if (gt == 0) { g_tot = 0.0; g_ticket = 0u; }

    int gp = gt >> 3;                 // pair index 0..8191
    int sl = gt & 7;                  // sub-lane within 8-lane group
    int layer = gp >> 11;
    int n = gp & (N_HALF - 1);

    const float4* ai = (const float4*)(ei + ((size_t)(layer * N_HALF + n)) * DIM);
    const float4* aj = (const float4*)(ej + ((size_t)(layer * N_HALF + n)) * DIM);
    // lane sl reads float4s sl, sl+8, sl+16, sl+24 (contiguous 128B per step)
    float4 fi[4], fj[4];
#pragma unroll
    for (int k = 0; k < 4; k++) fi[k] = ai[sl + 8 * k];
#pragma unroll
    for (int k = 0; k < 4; k++) fj[k] = aj[sl + 8 * k];

    float si = 0.f, sj = 0.f, dp = 0.f;
#pragma unroll
    for (int k = 0; k < 4; k++) {
        si += fi[k].x * fi[k].x + fi[k].y * fi[k].y + fi[k].z * fi[k].z + fi[k].w * fi[k].w;
        sj += fj[k].x * fj[k].x + fj[k].y * fj[k].y + fj[k].z * fj[k].z + fj[k].w * fj[k].w;
        dp += fi[k].x * fj[k].x + fi[k].y * fj[k].y + fi[k].z * fj[k].z + fi[k].w * fj[k].w;
    }
    // reduce across the 8 lanes of this group (xor 1,2,4 stays within group)
#pragma unroll
    for (int o = 1; o <= 4; o <<= 1) {
        si += __shfl_xor_sync(0xFFFFFFFFu, si, o);
        sj += __shfl_xor_sync(0xFFFFFFFFu, sj, o);
        dp += __shfl_xor_sync(0xFFFFFFFFu, dp, o);
    }
    float inv_i = 1.0f / fmaxf(sqrtf(si), 1e-12f);
    float inv_j = 1.0f / fmaxf(sqrtf(sj), 1e-12f);

    __half2* zi = (__half2*)(g_z + ((size_t)layer * N_FULL + n) * DIM);
    __half2* zj = (__half2*)(g_z + ((size_t)layer * N_FULL + N_HALF + n) * DIM);
#pragma unroll
    for (int k = 0; k < 4; k++) {
        int p = (sl + 8 * k) * 2;     // half2 index
        zi[p]     = __floats2half2_rn(fi[k].x * inv_i, fi[k].y * inv_i);
        zi[p + 1] = __floats2half2_rn(fi[k].z * inv_i, fi[k].w * inv_i);
        zj[p]     = __floats2half2_rn(fj[k].x * inv_j, fj[k].y * inv_j);
        zj[p + 1] = __floats2half2_rn(fj[k].z * inv_j, fj[k].w * inv_j);
    }
    if (sl == 0) g_pos[layer * N_HALF + n] = dp * inv_i * inv_j;
}

// ============================================================================
// Kernel 2: symmetric fused sim + exp + row/col sums (HMMA fp16, f16 accum).
// Upper-triangular tiles only. cp.async 2-stage K pipeline (64-col halves).
// 128 threads, 4 warps in 2x2, 64x64 per warp. 3 CTAs/SM.
// Epilogue fully packed: f16x2 exp + HADD2 partials + packed half2 shuffles.
// ============================================================================
static constexpr int SMEM_A = 0;
static constexpr int SMEM_B = 128 * 256;             // 32 KB
static constexpr int SMEM_TOTAL = 2 * 128 * 256;     // 64 KB

__global__ void __launch_bounds__(128, 3)
sim_kernel() {
    extern __shared__ char smem[];
    uint32_t sbase = smem_to_u32(smem);
    int tid = threadIdx.x;
    int wid = tid >> 5;
    int lane = tid & 31;

    int t = blockIdx.x;
    int layer = t / TRI_TILES;
    int u = t - layer * TRI_TILES;      // 0..527 upper-tri index
    int rowt = (int)((65.0f - sqrtf(65.0f * 65.0f - 8.0f * (float)u)) * 0.5f);
    while ((rowt + 1) * TDIM - ((rowt + 1) * rowt) / 2 <= u) rowt++;
    while (rowt * TDIM - (rowt * (rowt - 1)) / 2 > u) rowt--;
    int colt = rowt + (u - (rowt * TDIM - (rowt * (rowt - 1)) / 2));
    int r0 = rowt * TM;
    int c0 = colt * TN;
    bool diag_tile = (rowt == colt);

    const __half* zl = g_z + (size_t)layer * N_FULL * DIM;

    // ---- cp.async 2-stage pipeline: half h covers 16B-chunks h*8..h*8+7 ----
#pragma unroll
    for (int h = 0; h < 2; h++) {
#pragma unroll
        for (int it = 0; it < 8; it++) {
            int idx = tid + it * 128;        // 1024 chunks per tile-half
            int row = idx >> 3;
            int c = idx & 7;
            int ch = h * 8 + c;
            uint32_t dst_off = (uint32_t)row * 256 + (uint32_t)((ch ^ (row & 7)) * 16);
            cp_async16(sbase + SMEM_A + dst_off, zl + (size_t)(r0 + row) * DIM + ch * 8);
            cp_async16(sbase + SMEM_B + dst_off, zl + (size_t)(c0 + row) * DIM + ch * 8);
        }
        cp_async_commit();
    }

    // ---- Warp tiling: wm,wn in {0,1}; warp covers 64x64 ----
    int wm = wid >> 1;
    int wn = wid & 1;

    uint32_t acc[4][8][2];               // f16x2 accumulators
#pragma unroll
    for (int mt = 0; mt < 4; mt++)
#pragma unroll
        for (int nt = 0; nt < 8; nt++) { acc[mt][nt][0] = 0u; acc[mt][nt][1] = 0u; }

    int lr = lane & 7;
    int g = lane >> 3;
    int a_row_off = lr + ((g & 1) << 3);
    int a_chalf = g >> 1;
    int b_row_off = lr + ((lane >> 4) << 3);
    int b_chalf = (lane >> 3) & 1;

#pragma unroll
    for (int half = 0; half < 2; half++) {
        if (half == 0) cp_async_wait<1>(); else cp_async_wait<0>();
        __syncthreads();
#pragma unroll
        for (int kk = 0; kk < 4; kk++) {
            int ks = half * 4 + kk;
            uint32_t a[4][4];
#pragma unroll
            for (int mt = 0; mt < 4; mt++) {
                int r = wm * 64 + mt * 16 + a_row_off;
                int ch = 2 * ks + a_chalf;
                uint32_t addr = sbase + SMEM_A + (uint32_t)r * 256
                              + (uint32_t)((ch ^ (r & 7)) * 16);
                ldmatrix_x4(a[mt][0], a[mt][1], a[mt][2], a[mt][3], addr);
            }
            uint32_t b[8][2];
#pragma unroll
            for (int np = 0; np < 4; np++) {     // pairs of 8-col n-tiles
                int n = wn * 64 + np * 16 + b_row_off;
                int ch = 2 * ks + b_chalf;
                uint32_t addr = sbase + SMEM_B + (uint32_t)n * 256
                              + (uint32_t)((ch ^ (n & 7)) * 16);
                ldmatrix_x4(b[2 * np][0], b[2 * np][1], b[2 * np + 1][0], b[2 * np + 1][1], addr);
            }
#pragma unroll
            for (int mt = 0; mt < 4; mt++)
#pragma unroll
                for (int nt = 0; nt < 8; nt++)
                    mma_f16acc(acc[mt][nt], a[mt], b[nt]);
        }
    }

    // ---- Epilogue ----
    int q = lane >> 2;       // accum row within 8
    int qq = lane & 3;       // accum col quad
    float* S = g_S + layer * N_FULL;
    const __half2 scale_h2 = __float2half2_rn(EXP_SCALE);

    if (diag_tile) {
        // masked f32 path (identity diagonal lives here; only 32/528 tiles)
#pragma unroll
        for (int mt = 0; mt < 4; mt++) {
            int gr0 = r0 + wm * 64 + mt * 16 + q;
            int gr1 = gr0 + 8;
            float s0 = 0.0f, s1 = 0.0f;
#pragma unroll
            for (int nt = 0; nt < 8; nt++) {
                int gcb = c0 + wn * 64 + nt * 8 + qq * 2;
                float2 f01 = __half22float2(h2_exp2(__hmul2(*(__half2*)&acc[mt][nt][0], scale_h2)));
                float2 f23 = __half22float2(h2_exp2(__hmul2(*(__half2*)&acc[mt][nt][1], scale_h2)));
                if (gcb     != gr0) s0 += f01.x;
                if (gcb + 1 != gr0) s0 += f01.y;
                if (gcb     != gr1) s1 += f23.x;
                if (gcb + 1 != gr1) s1 += f23.y;
            }
            s0 += __shfl_xor_sync(0xFFFFFFFFu, s0, 1);
            s0 += __shfl_xor_sync(0xFFFFFFFFu, s0, 2);
            s1 += __shfl_xor_sync(0xFFFFFFFFu, s1, 1);
            s1 += __shfl_xor_sync(0xFFFFFFFFu, s1, 2);
            if (qq == 0) {
                atomicAdd(&S[gr0], s0);
                atomicAdd(&S[gr1], s1);
            }
        }
    } else {
        // fully packed path: e01 lanes share row gr0; e23 lanes share row gr1;
        // (e01 + e23) lanes are the two column partials.
        __half2 cs_h2[8];
#pragma unroll
        for (int nt = 0; nt < 8; nt++) cs_h2[nt] = __float2half2_rn(0.0f);
#pragma unroll
        for (int mt = 0; mt < 4; mt++) {
            int gr0 = r0 + wm * 64 + mt * 16 + q;
            __half2 r0h = __float2half2_rn(0.0f);
            __half2 r1h = __float2half2_rn(0.0f);
#pragma unroll
            for (int nt = 0; nt < 8; nt++) {
                __half2 e01 = h2_exp2(__hmul2(*(__half2*)&acc[mt][nt][0], scale_h2));
                __half2 e23 = h2_exp2(__hmul2(*(__half2*)&acc[mt][nt][1], scale_h2));
                r0h = __hadd2(r0h, e01);
                r1h = __hadd2(r1h, e23);
                cs_h2[nt] = __hadd2(cs_h2[nt], __hadd2(e01, e23));
            }
            // pack {row gr0 partial, row gr0+8 partial} into one half2, 2 packed shuffles
            __half2 rp = __halves2half2(__hadd(__low2half(r0h), __high2half(r0h)),
                                        __hadd(__low2half(r1h), __high2half(r1h)));
            rp = h2_shfl_add(rp, 1);
            rp = h2_shfl_add(rp, 2);
            if (qq == 0) {
                atomicAdd(&S[gr0],     __low2float(rp));
                atomicAdd(&S[gr0 + 8], __high2float(rp));
            }
        }
        // column sums: packed half2 shuffles over q (xor 4,8,16)
#pragma unroll
        for (int nt = 0; nt < 8; nt++) {
            __half2 c = cs_h2[nt];
            c = h2_shfl_add(c, 4);
            c = h2_shfl_add(c, 8);
            c = h2_shfl_add(c, 16);
            if (q == 0) {
                atomicAdd(&S[c0 + wn * 64 + nt * 8 + qq * 2],     __low2float(c));
                atomicAdd(&S[c0 + wn * 64 + nt * 8 + qq * 2 + 1], __high2float(c));
            }
        }
    }
}

// ============================================================================
// Kernel 3: loss reduction + last-block finalize
// ============================================================================
__global__ void reduce_kernel(const float* __restrict__ jv, float* __restrict__ out) {
    __shared__ float sh[256];
    __shared__ bool is_last;
    int tid = threadIdx.x;
    int i = blockIdx.x * 256 + tid;          // 0..16383
    int layer = i >> 12;
    int n = i & (N_FULL - 1);
    int m = n & (N_HALF - 1);
    float w = jv[m];
    float lp = logf(g_S[i]) - g_pos[layer * N_HALF + m] * TEMP_INV;
    sh[tid] = w * lp;
    __syncthreads();
    for (int o = 128; o; o >>= 1) {
        if (tid < o) sh[tid] += sh[tid + o];
        __syncthreads();
    }
    if (tid == 0) {
        atomicAdd(&g_tot, (double)sh[0]);
        __threadfence();
        unsigned int done = atomicAdd(&g_ticket, 1u);
        is_last = (done == REDUCE_BLOCKS - 1);
    }
    __syncthreads();

    if (is_last) {
        float num = 0.0f;
        for (int k = tid; k < N_HALF; k += 256) num += jv[k];
        sh[tid] = num;
        __syncthreads();
        for (int o = 128; o; o >>= 1) {
            if (tid < o) sh[tid] += sh[tid + o];
            __syncthreads();
        }
        if (tid == 0) {
            double tot = *((volatile double*)&g_tot);
            out[0] = (float)(tot / (2.0 * (double)sh[0]));
        }
    }
}

// ============================================================================
// Launch
// ============================================================================
extern "C" void kernel_launch(void* const* d_in, const int* in_sizes, int n_in,
                              void* d_out, int out_size) {
    const float* ei = (const float*)d_in[0];
    const float* ej = (const float*)d_in[1];
    const float* jv = (const float*)d_in[2];
    float* out = (float*)d_out;

    cudaFuncSetAttribute(sim_kernel, cudaFuncAttributeMaxDynamicSharedMemorySize, SMEM_TOTAL);

    norm_kernel<<<512, 128>>>(ei, ej);
    sim_kernel<<<L_LAYERS * TRI_TILES, 128, SMEM_TOTAL>>>();
    reduce_kernel<<<REDUCE_BLOCKS, 256>>>(jv, out);
}

// round 16
// speedup vs baseline: 1.0646x; 1.0116x over previous
#include <cuda_runtime.h>
#include <cuda_fp16.h>
#include <cstdint>

// ============================================================================
// Problem constants: l=4, B=64, K=32, D=128 -> N=2048 rows per side, 2N=4096
// ============================================================================
#define L_LAYERS 4
#define N_HALF   2048
#define N_FULL   4096
#define DIM      128
#define TEMP_INV 5.0f
#define EXP_SCALE 7.2134752044448169f   // (1/T)*log2(e)
#define SELF_TERM 148.4131591025766f    // exp(1/T * 1.0) subtracted analytically

// Tile config: 128x128 sim tile per CTA, 4 warps in 2(m) x 2(n), 64x64 each
#define TM 128
#define TN 128
#define TDIM 32                                 // tiles per side
#define TRI_TILES (TDIM * (TDIM + 1) / 2)       // 528 upper-tri tiles per layer

#define REDUCE_BLOCKS 64

// ============================================================================
// Device scratch (allocation-free rule: __device__ globals)
// ============================================================================
__device__ __half g_z[(size_t)L_LAYERS * N_FULL * DIM];         // normalized reps (fp16)
__device__ float g_pos[L_LAYERS * N_HALF];                      // fp32 positives (exact)
__device__ float g_S[L_LAYERS * N_FULL];                        // per-row exp sums
__device__ double g_tot;                                        // loss accumulator
__device__ unsigned int g_ticket;                               // last-block-done counter

// ============================================================================
// Helpers
// ============================================================================
__device__ __forceinline__ uint32_t smem_to_u32(const void* smem_ptr) {
    uint32_t addr;
    asm("{ .reg .u64 tmp; cvta.to.shared.u64 tmp, %1; cvt.u32.u64 %0, tmp; }"
        : "=r"(addr) : "l"(smem_ptr));
    return addr;
}

__device__ __forceinline__ void gdc_wait() {
    asm volatile("griddepcontrol.wait;" ::: "memory");
}
__device__ __forceinline__ void gdc_launch() {
    asm volatile("griddepcontrol.launch_dependents;" ::: "memory");
}

__device__ __forceinline__ void cp_async16(uint32_t dst, const void* src) {
    asm volatile("cp.async.cg.shared.global [%0], [%1], 16;"
                 :: "r"(dst), "l"(src) : "memory");
}
__device__ __forceinline__ void cp_async_commit() {
    asm volatile("cp.async.commit_group;" ::: "memory");
}
template <int N>
__device__ __forceinline__ void cp_async_wait() {
    asm volatile("cp.async.wait_group %0;" :: "n"(N) : "memory");
}

__device__ __forceinline__ void ldmatrix_x4(uint32_t& r0, uint32_t& r1,
                                            uint32_t& r2, uint32_t& r3, uint32_t addr) {
    asm volatile("ldmatrix.sync.aligned.m8n8.x4.shared.b16 {%0,%1,%2,%3}, [%4];"
                 : "=r"(r0), "=r"(r1), "=r"(r2), "=r"(r3) : "r"(addr));
}

// fp16 MMA with fp16 accumulate: m16n8k16, D/C are 2 regs (4 halves).
// reg0 = {c0, c1} @ row q; reg1 = {c2, c3} @ row q+8 (cols 2qq, 2qq+1).
__device__ __forceinline__ void mma_f16acc(uint32_t* d, const uint32_t* a, const uint32_t* b) {
    asm volatile(
        "mma.sync.aligned.m16n8k16.row.col.f16.f16.f16.f16 "
        "{%0,%1}, {%2,%3,%4,%5}, {%6,%7}, {%0,%1};"
        : "+r"(d[0]), "+r"(d[1])
        : "r"(a[0]), "r"(a[1]), "r"(a[2]), "r"(a[3]), "r"(b[0]), "r"(b[1]));
}

// two exponentials per MUFU op: ex2.approx.f16x2
__device__ __forceinline__ __half2 h2_exp2(__half2 x) {
    __half2 y;
    asm("ex2.approx.f16x2 %0, %1;" : "=r"(*(uint32_t*)&y) : "r"(*(uint32_t*)&x));
    return y;
}

// shuffle a __half2 (as uint32) and hadd2-combine
__device__ __forceinline__ __half2 h2_shfl_add(__half2 v, int mask) {
    uint32_t u = *(uint32_t*)&v;
    uint32_t o = __shfl_xor_sync(0xFFFFFFFFu, u, mask);
    return __hadd2(v, *(__half2*)&o);
}

// ============================================================================
// Kernel 1: L2-normalize -> fp16 g_z, fp32 positives, zero g_S/g_tot/g_ticket
// EIGHT lanes per (layer, n) pair (MLP=8, 3-level reduce). 512 blocks x 128.
// ============================================================================
__global__ void norm_kernel(const float* __restrict__ ei, const float* __restrict__ ej) {
    int gt = blockIdx.x * 128 + threadIdx.x;      // 0..65535
    if (gt < L_LAYERS * N_FULL) g_S[gt] = 0.0f;
    if (gt == 0) { g_tot = 0.0; g_ticket = 0u; }

    int gp = gt >> 3;                 // pair index 0..8191
    int sl = gt & 7;                  // sub-lane within 8-lane group
    int layer = gp >> 11;
    int n = gp & (N_HALF - 1);

    const float4* ai = (const float4*)(ei + ((size_t)(layer * N_HALF + n)) * DIM);
    const float4* aj = (const float4*)(ej + ((size_t)(layer * N_HALF + n)) * DIM);
    float4 fi[4], fj[4];
#pragma unroll
    for (int k = 0; k < 4; k++) fi[k] = ai[sl + 8 * k];
#pragma unroll
    for (int k = 0; k < 4; k++) fj[k] = aj[sl + 8 * k];

    float si = 0.f, sj = 0.f, dp = 0.f;
#pragma unroll
    for (int k = 0; k < 4; k++) {
        si += fi[k].x * fi[k].x + fi[k].y * fi[k].y + fi[k].z * fi[k].z + fi[k].w * fi[k].w;
        sj += fj[k].x * fj[k].x + fj[k].y * fj[k].y + fj[k].z * fj[k].z + fj[k].w * fj[k].w;
        dp += fi[k].x * fj[k].x + fi[k].y * fj[k].y + fi[k].z * fj[k].z + fi[k].w * fj[k].w;
    }
#pragma unroll
    for (int o = 1; o <= 4; o <<= 1) {
        si += __shfl_xor_sync(0xFFFFFFFFu, si, o);
        sj += __shfl_xor_sync(0xFFFFFFFFu, sj, o);
        dp += __shfl_xor_sync(0xFFFFFFFFu, dp, o);
    }
    float inv_i = 1.0f / fmaxf(sqrtf(si), 1e-12f);
    float inv_j = 1.0f / fmaxf(sqrtf(sj), 1e-12f);

    __half2* zi = (__half2*)(g_z + ((size_t)layer * N_FULL + n) * DIM);
    __half2* zj = (__half2*)(g_z + ((size_t)layer * N_FULL + N_HALF + n) * DIM);
#pragma unroll
    for (int k = 0; k < 4; k++) {
        int p = (sl + 8 * k) * 2;     // half2 index
        zi[p]     = __floats2half2_rn(fi[k].x * inv_i, fi[k].y * inv_i);
        zi[p + 1] = __floats2half2_rn(fi[k].z * inv_i, fi[k].w * inv_i);
        zj[p]     = __floats2half2_rn(fj[k].x * inv_j, fj[k].y * inv_j);
        zj[p + 1] = __floats2half2_rn(fj[k].z * inv_j, fj[k].w * inv_j);
    }
    if (sl == 0) g_pos[layer * N_HALF + n] = dp * inv_i * inv_j;

    gdc_launch();   // PDL: allow sim to begin launching
}

// ============================================================================
// Kernel 2: symmetric fused sim + exp + row/col sums (HMMA fp16, f16 accum).
// Upper-triangular tiles only. cp.async 2-stage K pipeline (64-col halves).
// 128 threads, 4 warps in 2x2, 64x64 per warp. 3 CTAs/SM.
// Single packed epilogue path; the self-diagonal term is included in row sums
// and subtracted analytically in reduce (log(S - e^5)).
// ============================================================================
static constexpr int SMEM_A = 0;
static constexpr int SMEM_B = 128 * 256;             // 32 KB
static constexpr int SMEM_TOTAL = 2 * 128 * 256;     // 64 KB

__global__ void __launch_bounds__(128, 3)
sim_kernel() {
    extern __shared__ char smem[];
    uint32_t sbase = smem_to_u32(smem);
    int tid = threadIdx.x;
    int wid = tid >> 5;
    int lane = tid & 31;

    int t = blockIdx.x;
    int layer = t / TRI_TILES;
    int u = t - layer * TRI_TILES;      // 0..527 upper-tri index
    int rowt = (int)((65.0f - sqrtf(65.0f * 65.0f - 8.0f * (float)u)) * 0.5f);
    while ((rowt + 1) * TDIM - ((rowt + 1) * rowt) / 2 <= u) rowt++;
    while (rowt * TDIM - (rowt * (rowt - 1)) / 2 > u) rowt--;
    int colt = rowt + (u - (rowt * TDIM - (rowt * (rowt - 1)) / 2));
    int r0 = rowt * TM;
    int c0 = colt * TN;
    bool diag_tile = (rowt == colt);

    const __half* zl = g_z + (size_t)layer * N_FULL * DIM;

    gdc_wait();   // PDL: norm's g_z / g_S writes must be visible

    // ---- cp.async 2-stage pipeline: half h covers 16B-chunks h*8..h*8+7 ----
#pragma unroll
    for (int h = 0; h < 2; h++) {
#pragma unroll
        for (int it = 0; it < 8; it++) {
            int idx = tid + it * 128;        // 1024 chunks per tile-half
            int row = idx >> 3;
            int c = idx & 7;
            int ch = h * 8 + c;
            uint32_t dst_off = (uint32_t)row * 256 + (uint32_t)((ch ^ (row & 7)) * 16);
            cp_async16(sbase + SMEM_A + dst_off, zl + (size_t)(r0 + row) * DIM + ch * 8);
            cp_async16(sbase + SMEM_B + dst_off, zl + (size_t)(c0 + row) * DIM + ch * 8);
        }
        cp_async_commit();
    }

    // ---- Warp tiling: wm,wn in {0,1}; warp covers 64x64 ----
    int wm = wid >> 1;
    int wn = wid & 1;

    uint32_t acc[4][8][2];               // f16x2 accumulators
#pragma unroll
    for (int mt = 0; mt < 4; mt++)
#pragma unroll
        for (int nt = 0; nt < 8; nt++) { acc[mt][nt][0] = 0u; acc[mt][nt][1] = 0u; }

    int lr = lane & 7;
    int g = lane >> 3;
    int a_row_off = lr + ((g & 1) << 3);
    int a_chalf = g >> 1;
    int b_row_off = lr + ((lane >> 4) << 3);
    int b_chalf = (lane >> 3) & 1;

#pragma unroll
    for (int half = 0; half < 2; half++) {
        if (half == 0) cp_async_wait<1>(); else cp_async_wait<0>();
        __syncthreads();
#pragma unroll
        for (int kk = 0; kk < 4; kk++) {
            int ks = half * 4 + kk;
            uint32_t a[4][4];
#pragma unroll
            for (int mt = 0; mt < 4; mt++) {
                int r = wm * 64 + mt * 16 + a_row_off;
                int ch = 2 * ks + a_chalf;
                uint32_t addr = sbase + SMEM_A + (uint32_t)r * 256
                              + (uint32_t)((ch ^ (r & 7)) * 16);
                ldmatrix_x4(a[mt][0], a[mt][1], a[mt][2], a[mt][3], addr);
            }
            uint32_t b[8][2];
#pragma unroll
            for (int np = 0; np < 4; np++) {     // pairs of 8-col n-tiles
                int n = wn * 64 + np * 16 + b_row_off;
                int ch = 2 * ks + b_chalf;
                uint32_t addr = sbase + SMEM_B + (uint32_t)n * 256
                              + (uint32_t)((ch ^ (n & 7)) * 16);
                ldmatrix_x4(b[2 * np][0], b[2 * np][1], b[2 * np + 1][0], b[2 * np + 1][1], addr);
            }
#pragma unroll
            for (int mt = 0; mt < 4; mt++)
#pragma unroll
                for (int nt = 0; nt < 8; nt++)
                    mma_f16acc(acc[mt][nt], a[mt], b[nt]);
        }
    }

    // ---- Epilogue (single packed path; self-term handled in reduce) ----
    int q = lane >> 2;       // accum row within 8
    int qq = lane & 3;       // accum col quad
    float* S = g_S + layer * N_FULL;
    const __half2 scale_h2 = __float2half2_rn(EXP_SCALE);

    __half2 cs_h2[8];
#pragma unroll
    for (int nt = 0; nt < 8; nt++) cs_h2[nt] = __float2half2_rn(0.0f);
#pragma unroll
    for (int mt = 0; mt < 4; mt++) {
        int gr0 = r0 + wm * 64 + mt * 16 + q;
        __half2 r0h = __float2half2_rn(0.0f);
        __half2 r1h = __float2half2_rn(0.0f);
#pragma unroll
        for (int nt = 0; nt < 8; nt++) {
            __half2 e01 = h2_exp2(__hmul2(*(__half2*)&acc[mt][nt][0], scale_h2));
            __half2 e23 = h2_exp2(__hmul2(*(__half2*)&acc[mt][nt][1], scale_h2));
            r0h = __hadd2(r0h, e01);
            r1h = __hadd2(r1h, e23);
            if (!diag_tile) cs_h2[nt] = __hadd2(cs_h2[nt], __hadd2(e01, e23));
        }
        // pack {row gr0 partial, row gr0+8 partial} into one half2, 2 packed shuffles
        __half2 rp = __halves2half2(__hadd(__low2half(r0h), __high2half(r0h)),
                                    __hadd(__low2half(r1h), __high2half(r1h)));
        rp = h2_shfl_add(rp, 1);
        rp = h2_shfl_add(rp, 2);
        if (qq == 0) {
            atomicAdd(&S[gr0],     __low2float(rp));
            atomicAdd(&S[gr0 + 8], __high2float(rp));
        }
    }
    // column sums via symmetry (off-diagonal tiles only; diag tiles already
    // counted both orientations in their full-square row sums)
    if (!diag_tile) {
#pragma unroll
        for (int nt = 0; nt < 8; nt++) {
            __half2 c = cs_h2[nt];
            c = h2_shfl_add(c, 4);
            c = h2_shfl_add(c, 8);
            c = h2_shfl_add(c, 16);
            if (q == 0) {
                atomicAdd(&S[c0 + wn * 64 + nt * 8 + qq * 2],     __low2float(c));
                atomicAdd(&S[c0 + wn * 64 + nt * 8 + qq * 2 + 1], __high2float(c));
            }
        }
    }

    gdc_launch();   // PDL: allow reduce to begin launching
}

// ============================================================================
// Kernel 3: loss reduction + last-block finalize.
// Subtracts the analytic self-term exp(1/T) from each row sum.
// ============================================================================
__global__ void reduce_kernel(const float* __restrict__ jv, float* __restrict__ out) {
    __shared__ float sh[256];
    __shared__ bool is_last;
    int tid = threadIdx.x;
    int i = blockIdx.x * 256 + tid;          // 0..16383
    int layer = i >> 12;
    int n = i & (N_FULL - 1);
    int m = n & (N_HALF - 1);

    gdc_wait();   // PDL: sim's g_S atomics must be visible

    float w = jv[m];
    float lp = logf(g_S[i] - SELF_TERM) - g_pos[layer * N_HALF + m] * TEMP_INV;
    sh[tid] = w * lp;
    __syncthreads();
    for (int o = 128; o; o >>= 1) {
        if (tid < o) sh[tid] += sh[tid + o];
        __syncthreads();
    }
    if (tid == 0) {
        atomicAdd(&g_tot, (double)sh[0]);
        __threadfence();
        unsigned int done = atomicAdd(&g_ticket, 1u);
        is_last = (done == REDUCE_BLOCKS - 1);
    }
    __syncthreads();

    if (is_last) {
        float num = 0.0f;
        for (int k = tid; k < N_HALF; k += 256) num += jv[k];
        sh[tid] = num;
        __syncthreads();
        for (int o = 128; o; o >>= 1) {
            if (tid < o) sh[tid] += sh[tid + o];
            __syncthreads();
        }
        if (tid == 0) {
            double tot = *((volatile double*)&g_tot);
            out[0] = (float)(tot / (2.0 * (double)sh[0]));
        }
    }
}

// ============================================================================
// Launch (PDL-chained: norm -> sim -> reduce)
// ============================================================================
extern "C" void kernel_launch(void* const* d_in, const int* in_sizes, int n_in,
                              void* d_out, int out_size) {
    const float* ei = (const float*)d_in[0];
    const float* ej = (const float*)d_in[1];
    const float* jv = (const float*)d_in[2];
    float* out = (float*)d_out;

    cudaFuncSetAttribute(sim_kernel, cudaFuncAttributeMaxDynamicSharedMemorySize, SMEM_TOTAL);

    norm_kernel<<<512, 128>>>(ei, ej);

    cudaLaunchAttribute pdl_attr[1];
    pdl_attr[0].id = cudaLaunchAttributeProgrammaticStreamSerialization;
    pdl_attr[0].val.programmaticStreamSerializationAllowed = 1;

    {
        cudaLaunchConfig_t cfg = {};
        cfg.gridDim = dim3(L_LAYERS * TRI_TILES, 1, 1);
        cfg.blockDim = dim3(128, 1, 1);
        cfg.dynamicSmemBytes = SMEM_TOTAL;
        cfg.stream = 0;
        cfg.attrs = pdl_attr;
        cfg.numAttrs = 1;
        cudaLaunchKernelEx(&cfg, sim_kernel);
    }
    {
        cudaLaunchConfig_t cfg = {};
        cfg.gridDim = dim3(REDUCE_BLOCKS, 1, 1);
        cfg.blockDim = dim3(256, 1, 1);
        cfg.dynamicSmemBytes = 0;
        cfg.stream = 0;
        cfg.attrs = pdl_attr;
        cfg.numAttrs = 1;
        cudaLaunchKernelEx(&cfg, reduce_kernel, jv, out);
    }
}

// round 17
// speedup vs baseline: 1.0750x; 1.0097x over previous
#include <cuda_runtime.h>
#include <cuda_fp16.h>
#include <cstdint>

// ============================================================================
// Problem constants: l=4, B=64, K=32, D=128 -> N=2048 rows per side, 2N=4096
// ============================================================================
#define L_LAYERS 4
#define N_HALF   2048
#define N_FULL   4096
#define DIM      128
#define TEMP_INV 5.0f
#define EXP_SCALE 7.2134752044448169f   // (1/T)*log2(e)
#define SELF_TERM 148.4131591025766f    // exp(1/T * 1.0) subtracted analytically

// Tile config: 128x128 sim tile per CTA, 4 warps in 2(m) x 2(n), 64x64 each
#define TM 128
#define TN 128
#define TDIM 32                                 // tiles per side
#define TRI_TILES (TDIM * (TDIM + 1) / 2)       // 528 upper-tri tiles per layer

#define REDUCE_BLOCKS 64

// ============================================================================
// Device scratch (allocation-free rule: __device__ globals)
// ============================================================================
__device__ __half g_z[(size_t)L_LAYERS * N_FULL * DIM];         // normalized reps (fp16)
__device__ float g_pos[L_LAYERS * N_HALF];                      // fp32 positives (exact)
__device__ float g_S[L_LAYERS * N_FULL];                        // per-row exp sums
__device__ double g_tot;                                        // loss accumulator
__device__ unsigned int g_ticket;                               // last-block-done counter

// ============================================================================
// Helpers
// ============================================================================
__device__ __forceinline__ uint32_t smem_to_u32(const void* smem_ptr) {
    uint32_t addr;
    asm("{ .reg .u64 tmp; cvta.to.shared.u64 tmp, %1; cvt.u32.u64 %0, tmp; }"
        : "=r"(addr) : "l"(smem_ptr));
    return addr;
}

__device__ __forceinline__ void gdc_wait() {
    asm volatile("griddepcontrol.wait;" ::: "memory");
}
__device__ __forceinline__ void gdc_launch() {
    asm volatile("griddepcontrol.launch_dependents;" ::: "memory");
}

__device__ __forceinline__ void cp_async16(uint32_t dst, const void* src) {
    asm volatile("cp.async.cg.shared.global [%0], [%1], 16;"
                 :: "r"(dst), "l"(src) : "memory");
}
__device__ __forceinline__ void cp_async_commit() {
    asm volatile("cp.async.commit_group;" ::: "memory");
}
template <int N>
__device__ __forceinline__ void cp_async_wait() {
    asm volatile("cp.async.wait_group %0;" :: "n"(N) : "memory");
}

__device__ __forceinline__ void ldmatrix_x4(uint32_t& r0, uint32_t& r1,
                                            uint32_t& r2, uint32_t& r3, uint32_t addr) {
    asm volatile("ldmatrix.sync.aligned.m8n8.x4.shared.b16 {%0,%1,%2,%3}, [%4];"
                 : "=r"(r0), "=r"(r1), "=r"(r2), "=r"(r3) : "r"(addr));
}

// fp16 MMA with fp16 accumulate: m16n8k16, D/C are 2 regs (4 halves).
// reg0 = {c0, c1} @ row q; reg1 = {c2, c3} @ row q+8 (cols 2qq, 2qq+1).
__device__ __forceinline__ void mma_f16acc(uint32_t* d, const uint32_t* a, const uint32_t* b) {
    asm volatile(
        "mma.sync.aligned.m16n8k16.row.col.f16.f16.f16.f16 "
        "{%0,%1}, {%2,%3,%4,%5}, {%6,%7}, {%0,%1};"
        : "+r"(d[0]), "+r"(d[1])
        : "r"(a[0]), "r"(a[1]), "r"(a[2]), "r"(a[3]), "r"(b[0]), "r"(b[1]));
}

// two exponentials per MUFU op: ex2.approx.f16x2
__device__ __forceinline__ __half2 h2_exp2(__half2 x) {
    __half2 y;
    asm("ex2.approx.f16x2 %0, %1;" : "=r"(*(uint32_t*)&y) : "r"(*(uint32_t*)&x));
    return y;
}

// shuffle a __half2 (as uint32) and hadd2-combine
__device__ __forceinline__ __half2 h2_shfl_add(__half2 v, int mask) {
    uint32_t u = *(uint32_t*)&v;
    uint32_t o = __shfl_xor_sync(0xFFFFFFFFu, u, mask);
    return __hadd2(v, *(__half2*)&o);
}

// ============================================================================
// Kernel 1: L2-normalize -> fp16 g_z, fp32 positives, zero g_S/g_tot/g_ticket
// SIXTEEN lanes per (layer, n) pair: each lane loads 2+2 float4, 4-level
// shuffle reduce (xor 1,2,4,8). 1024 blocks x 128 threads -> ~7 CTAs/SM.
// ============================================================================
__global__ void norm_kernel(const float* __restrict__ ei, const float* __restrict__ ej) {
    int gt = blockIdx.x * 128 + threadIdx.x;      // 0..131071
    if (gt < L_LAYERS * N_FULL) g_S[gt] = 0.0f;
    if (gt == 0) { g_tot = 0.0; g_ticket = 0u; }

    int gp = gt >> 4;                 // pair index 0..8191
    int sl = gt & 15;                 // sub-lane within 16-lane group
    int layer = gp >> 11;
    int n = gp & (N_HALF - 1);

    const float4* ai = (const float4*)(ei + ((size_t)(layer * N_HALF + n)) * DIM);
    const float4* aj = (const float4*)(ej + ((size_t)(layer * N_HALF + n)) * DIM);
    // lane sl reads float4s sl, sl+16 (contiguous 256B per step)
    float4 fi[2], fj[2];
#pragma unroll
    for (int k = 0; k < 2; k++) fi[k] = ai[sl + 16 * k];
#pragma unroll
    for (int k = 0; k < 2; k++) fj[k] = aj[sl + 16 * k];

    float si = 0.f, sj = 0.f, dp = 0.f;
#pragma unroll
    for (int k = 0; k < 2; k++) {
        si += fi[k].x * fi[k].x + fi[k].y * fi[k].y + fi[k].z * fi[k].z + fi[k].w * fi[k].w;
        sj += fj[k].x * fj[k].x + fj[k].y * fj[k].y + fj[k].z * fj[k].z + fj[k].w * fj[k].w;
        dp += fi[k].x * fj[k].x + fi[k].y * fj[k].y + fi[k].z * fj[k].z + fi[k].w * fj[k].w;
    }
    // reduce across the 16 lanes of this group (xor 1,2,4,8 stays within group)
#pragma unroll
    for (int o = 1; o <= 8; o <<= 1) {
        si += __shfl_xor_sync(0xFFFFFFFFu, si, o);
        sj += __shfl_xor_sync(0xFFFFFFFFu, sj, o);
        dp += __shfl_xor_sync(0xFFFFFFFFu, dp, o);
    }
    float inv_i = 1.0f / fmaxf(sqrtf(si), 1e-12f);
    float inv_j = 1.0f / fmaxf(sqrtf(sj), 1e-12f);

    __half2* zi = (__half2*)(g_z + ((size_t)layer * N_FULL + n) * DIM);
    __half2* zj = (__half2*)(g_z + ((size_t)layer * N_FULL + N_HALF + n) * DIM);
#pragma unroll
    for (int k = 0; k < 2; k++) {
        int p = (sl + 16 * k) * 2;    // half2 index
        zi[p]     = __floats2half2_rn(fi[k].x * inv_i, fi[k].y * inv_i);
        zi[p + 1] = __floats2half2_rn(fi[k].z * inv_i, fi[k].w * inv_i);
        zj[p]     = __floats2half2_rn(fj[k].x * inv_j, fj[k].y * inv_j);
        zj[p + 1] = __floats2half2_rn(fj[k].z * inv_j, fj[k].w * inv_j);
    }
    if (sl == 0) g_pos[layer * N_HALF + n] = dp * inv_i * inv_j;

    gdc_launch();   // PDL: allow sim to begin launching
}

// ============================================================================
// Kernel 2: symmetric fused sim + exp + row/col sums (HMMA fp16, f16 accum).
// Upper-triangular tiles only. cp.async 2-stage K pipeline (64-col halves).
// 128 threads, 4 warps in 2x2, 64x64 per warp. 3 CTAs/SM.
// Single packed epilogue path; the self-diagonal term is included in row sums
// and subtracted analytically in reduce (log(S - e^5)).
// ============================================================================
static constexpr int SMEM_A = 0;
static constexpr int SMEM_B = 128 * 256;             // 32 KB
static constexpr int SMEM_TOTAL = 2 * 128 * 256;     // 64 KB

__global__ void __launch_bounds__(128, 3)
sim_kernel() {
    extern __shared__ char smem[];
    uint32_t sbase = smem_to_u32(smem);
    int tid = threadIdx.x;
    int wid = tid >> 5;
    int lane = tid & 31;

    int t = blockIdx.x;
    int layer = t / TRI_TILES;
    int u = t - layer * TRI_TILES;      // 0..527 upper-tri index
    int rowt = (int)((65.0f - sqrtf(65.0f * 65.0f - 8.0f * (float)u)) * 0.5f);
    while ((rowt + 1) * TDIM - ((rowt + 1) * rowt) / 2 <= u) rowt++;
    while (rowt * TDIM - (rowt * (rowt - 1)) / 2 > u) rowt--;
    int colt = rowt + (u - (rowt * TDIM - (rowt * (rowt - 1)) / 2));
    int r0 = rowt * TM;
    int c0 = colt * TN;
    bool diag_tile = (rowt == colt);

    const __half* zl = g_z + (size_t)layer * N_FULL * DIM;

    gdc_wait();   // PDL: norm's g_z / g_S writes must be visible

    // ---- cp.async 2-stage pipeline: half h covers 16B-chunks h*8..h*8+7 ----
#pragma unroll
    for (int h = 0; h < 2; h++) {
#pragma unroll
        for (int it = 0; it < 8; it++) {
            int idx = tid + it * 128;        // 1024 chunks per tile-half
            int row = idx >> 3;
            int c = idx & 7;
            int ch = h * 8 + c;
            uint32_t dst_off = (uint32_t)row * 256 + (uint32_t)((ch ^ (row & 7)) * 16);
            cp_async16(sbase + SMEM_A + dst_off, zl + (size_t)(r0 + row) * DIM + ch * 8);
            cp_async16(sbase + SMEM_B + dst_off, zl + (size_t)(c0 + row) * DIM + ch * 8);
        }
        cp_async_commit();
    }

    // ---- Warp tiling: wm,wn in {0,1}; warp covers 64x64 ----
    int wm = wid >> 1;
    int wn = wid & 1;

    uint32_t acc[4][8][2];               // f16x2 accumulators
#pragma unroll
    for (int mt = 0; mt < 4; mt++)
#pragma unroll
        for (int nt = 0; nt < 8; nt++) { acc[mt][nt][0] = 0u; acc[mt][nt][1] = 0u; }

    int lr = lane & 7;
    int g = lane >> 3;
    int a_row_off = lr + ((g & 1) << 3);
    int a_chalf = g >> 1;
    int b_row_off = lr + ((lane >> 4) << 3);
    int b_chalf = (lane >> 3) & 1;

#pragma unroll
    for (int half = 0; half < 2; half++) {
        if (half == 0) cp_async_wait<1>(); else cp_async_wait<0>();
        __syncthreads();
#pragma unroll
        for (int kk = 0; kk < 4; kk++) {
            int ks = half * 4 + kk;
            uint32_t a[4][4];
#pragma unroll
            for (int mt = 0; mt < 4; mt++) {
                int r = wm * 64 + mt * 16 + a_row_off;
                int ch = 2 * ks + a_chalf;
                uint32_t addr = sbase + SMEM_A + (uint32_t)r * 256
                              + (uint32_t)((ch ^ (r & 7)) * 16);
                ldmatrix_x4(a[mt][0], a[mt][1], a[mt][2], a[mt][3], addr);
            }
            uint32_t b[8][2];
#pragma unroll
            for (int np = 0; np < 4; np++) {     // pairs of 8-col n-tiles
                int n = wn * 64 + np * 16 + b_row_off;
                int ch = 2 * ks + b_chalf;
                uint32_t addr = sbase + SMEM_B + (uint32_t)n * 256
                              + (uint32_t)((ch ^ (n & 7)) * 16);
                ldmatrix_x4(b[2 * np][0], b[2 * np][1], b[2 * np + 1][0], b[2 * np + 1][1], addr);
            }
#pragma unroll
            for (int mt = 0; mt < 4; mt++)
#pragma unroll
                for (int nt = 0; nt < 8; nt++)
                    mma_f16acc(acc[mt][nt], a[mt], b[nt]);
        }
    }

    // ---- Epilogue (single packed path; self-term handled in reduce) ----
    int q = lane >> 2;       // accum row within 8
    int qq = lane & 3;       // accum col quad
    float* S = g_S + layer * N_FULL;
    const __half2 scale_h2 = __float2half2_rn(EXP_SCALE);

    __half2 cs_h2[8];
#pragma unroll
    for (int nt = 0; nt < 8; nt++) cs_h2[nt] = __float2half2_rn(0.0f);
#pragma unroll
    for (int mt = 0; mt < 4; mt++) {
        int gr0 = r0 + wm * 64 + mt * 16 + q;
        __half2 r0h = __float2half2_rn(0.0f);
        __half2 r1h = __float2half2_rn(0.0f);
#pragma unroll
        for (int nt = 0; nt < 8; nt++) {
            __half2 e01 = h2_exp2(__hmul2(*(__half2*)&acc[mt][nt][0], scale_h2));
            __half2 e23 = h2_exp2(__hmul2(*(__half2*)&acc[mt][nt][1], scale_h2));
            r0h = __hadd2(r0h, e01);
            r1h = __hadd2(r1h, e23);
            if (!diag_tile) cs_h2[nt] = __hadd2(cs_h2[nt], __hadd2(e01, e23));
        }
        // pack {row gr0 partial, row gr0+8 partial} into one half2, 2 packed shuffles
        __half2 rp = __halves2half2(__hadd(__low2half(r0h), __high2half(r0h)),
                                    __hadd(__low2half(r1h), __high2half(r1h)));
        rp = h2_shfl_add(rp, 1);
        rp = h2_shfl_add(rp, 2);
        if (qq == 0) {
            atomicAdd(&S[gr0],     __low2float(rp));
            atomicAdd(&S[gr0 + 8], __high2float(rp));
        }
    }
    // column sums via symmetry (off-diagonal tiles only; diag tiles already
    // counted both orientations in their full-square row sums)
    if (!diag_tile) {
#pragma unroll
        for (int nt = 0; nt < 8; nt++) {
            __half2 c = cs_h2[nt];
            c = h2_shfl_add(c, 4);
            c = h2_shfl_add(c, 8);
            c = h2_shfl_add(c, 16);
            if (q == 0) {
                atomicAdd(&S[c0 + wn * 64 + nt * 8 + qq * 2],     __low2float(c));
                atomicAdd(&S[c0 + wn * 64 + nt * 8 + qq * 2 + 1], __high2float(c));
            }
        }
    }

    gdc_launch();   // PDL: allow reduce to begin launching
}

// ============================================================================
// Kernel 3: loss reduction + last-block finalize.
// Subtracts the analytic self-term exp(1/T) from each row sum.
// ============================================================================
__global__ void reduce_kernel(const float* __restrict__ jv, float* __restrict__ out) {
    __shared__ float sh[256];
    __shared__ bool is_last;
    int tid = threadIdx.x;
    int i = blockIdx.x * 256 + tid;          // 0..16383
    int layer = i >> 12;
    int n = i & (N_FULL - 1);
    int m = n & (N_HALF - 1);

    gdc_wait();   // PDL: sim's g_S atomics must be visible

    float w = jv[m];
    float lp = logf(g_S[i] - SELF_TERM) - g_pos[layer * N_HALF + m] * TEMP_INV;
    sh[tid] = w * lp;
    __syncthreads();
    for (int o = 128; o; o >>= 1) {
        if (tid < o) sh[tid] += sh[tid + o];
        __syncthreads();
    }
    if (tid == 0) {
        atomicAdd(&g_tot, (double)sh[0]);
        __threadfence();
        unsigned int done = atomicAdd(&g_ticket, 1u);
        is_last = (done == REDUCE_BLOCKS - 1);
    }
    __syncthreads();

    if (is_last) {
        float num = 0.0f;
        for (int k = tid; k < N_HALF; k += 256) num += jv[k];
        sh[tid] = num;
        __syncthreads();
        for (int o = 128; o; o >>= 1) {
            if (tid < o) sh[tid] += sh[tid + o];
            __syncthreads();
        }
        if (tid == 0) {
            double tot = *((volatile double*)&g_tot);
            out[0] = (float)(tot / (2.0 * (double)sh[0]));
        }
    }
}

// ============================================================================
// Launch (PDL-chained: norm -> sim -> reduce)
// ============================================================================
extern "C" void kernel_launch(void* const* d_in, const int* in_sizes, int n_in,
                              void* d_out, int out_size) {
    const float* ei = (const float*)d_in[0];
    const float* ej = (const float*)d_in[1];
    const float* jv = (const float*)d_in[2];
    float* out = (float*)d_out;

    cudaFuncSetAttribute(sim_kernel, cudaFuncAttributeMaxDynamicSharedMemorySize, SMEM_TOTAL);

    norm_kernel<<<1024, 128>>>(ei, ej);

    cudaLaunchAttribute pdl_attr[1];
    pdl_attr[0].id = cudaLaunchAttributeProgrammaticStreamSerialization;
    pdl_attr[0].val.programmaticStreamSerializationAllowed = 1;

    {
        cudaLaunchConfig_t cfg = {};
        cfg.gridDim = dim3(L_LAYERS * TRI_TILES, 1, 1);
        cfg.blockDim = dim3(128, 1, 1);
        cfg.dynamicSmemBytes = SMEM_TOTAL;
        cfg.stream = 0;
        cfg.attrs = pdl_attr;
        cfg.numAttrs = 1;
        cudaLaunchKernelEx(&cfg, sim_kernel);
    }
    {
        cudaLaunchConfig_t cfg = {};
        cfg.gridDim = dim3(REDUCE_BLOCKS, 1, 1);
        cfg.blockDim = dim3(256, 1, 1);
        cfg.dynamicSmemBytes = 0;
        cfg.stream = 0;
        cfg.attrs = pdl_attr;
        cfg.numAttrs = 1;
        cudaLaunchKernelEx(&cfg, reduce_kernel, jv, out);
    }
}